// round 12
// baseline (speedup 1.0000x reference)
#include <cuda_runtime.h>
#include <cuda_fp16.h>
#include <math.h>
#include <stdint.h>

#define Bdim 32768
#define Ndim 2048
#define Hdim 512

// ---------------- scratch (device globals; no allocation allowed) ----------------
__device__ __align__(16) float g_mn[Ndim * Hdim];            // normalized memory fp32
__device__ float g_zinv[Bdim];
__device__ __align__(16) __half g_zh[(size_t)Bdim * Hdim];   // normalized z fp16
__device__ __align__(16) __half g_mh[Ndim * Hdim];           // normalized mem fp16
__device__ __align__(16) __half g_mth[Hdim * Ndim];          // mem^T fp16 (raw mem)
__device__ __align__(16) __half g_Wh[(size_t)Bdim * Ndim];   // exp(sim) fp16
__device__ __align__(16) float g_blkmax[(size_t)Bdim * 16];  // per (row, 128-col block) max of W (keyenc)
__device__ float g_rowsum[Bdim];
__device__ unsigned long long g_rowmax[Bdim];                // (keyenc(val)<<32)|idx
__device__ unsigned int g_colmax[Ndim];
__device__ unsigned int g_cnt[Ndim];
__device__ unsigned int g_off[Ndim];
__device__ unsigned int g_rowlist[Bdim];

// ---------------- helpers ----------------
__device__ __forceinline__ unsigned int keyenc(float f) {
    unsigned int b = __float_as_uint(f);
    return (b & 0x80000000u) ? ~b : (b | 0x80000000u);
}
__device__ __forceinline__ float keydec(unsigned int v) {
    unsigned int b = (v & 0x80000000u) ? (v ^ 0x80000000u) : ~v;
    return __uint_as_float(b);
}
__device__ __forceinline__ unsigned int pkh(__half a, __half b) {
    return ((unsigned int)__half_as_ushort(b) << 16) | (unsigned int)__half_as_ushort(a);
}
__device__ __forceinline__ uint32_t smem_u32(const void* p) {
    uint32_t a;
    asm("{ .reg .u64 t; cvta.to.shared.u64 t, %1; cvt.u32.u64 %0, t; }" : "=r"(a) : "l"(p));
    return a;
}

__device__ __forceinline__ void cp16(uint32_t d, const void* s) {
    asm volatile("cp.async.cg.shared.global [%0], [%1], 16;" :: "r"(d), "l"(s));
}
#define CP_COMMIT() asm volatile("cp.async.commit_group;" ::: "memory")
#define CP_WAIT(n)  asm volatile("cp.async.wait_group %0;" :: "n"(n) : "memory")

__device__ __forceinline__ void ldsm4(uint32_t* r, uint32_t a) {
    asm volatile("ldmatrix.sync.aligned.m8n8.x4.shared.b16 {%0,%1,%2,%3}, [%4];"
        : "=r"(r[0]), "=r"(r[1]), "=r"(r[2]), "=r"(r[3]) : "r"(a));
}
__device__ __forceinline__ void mma16816(float* c, const uint32_t* a, const uint32_t* b) {
    asm volatile(
        "mma.sync.aligned.m16n8k16.row.col.f32.f16.f16.f32 "
        "{%0,%1,%2,%3},{%4,%5,%6,%7},{%8,%9},{%0,%1,%2,%3};"
        : "+f"(c[0]), "+f"(c[1]), "+f"(c[2]), "+f"(c[3])
        : "r"(a[0]), "r"(a[1]), "r"(a[2]), "r"(a[3]), "r"(b[0]), "r"(b[1]));
}

// ---------------- normalize memory + zero scratch (incl. blkmax) ----------------
__global__ void k_norm_mem(const float* __restrict__ mem) {
    int i = blockIdx.x;
    int t = threadIdx.x;
    __shared__ float red[256];
    const float* r = mem + (size_t)i * Hdim;
    float v0 = r[t];
    float v1 = r[t + 256];
    red[t] = v0 * v0 + v1 * v1;
    __syncthreads();
    for (int s = 128; s > 0; s >>= 1) {
        if (t < s) red[t] += red[t + s];
        __syncthreads();
    }
    float inv = 1.0f / fmaxf(sqrtf(red[0]), 1e-12f);
    float n0 = v0 * inv, n1 = v1 * inv;
    size_t b = (size_t)i * Hdim + t;
    g_mn[b] = n0; g_mn[b + 256] = n1;
    g_mh[b] = __float2half_rn(n0);
    g_mh[b + 256] = __float2half_rn(n1);
    // scratch zeroing: 2048 blocks cover Bdim rows (16/block) and blkmax (256/block)
    ((unsigned int*)g_blkmax)[i * 256 + t] = 0u;
    if (t < 16) {
        int j = i * 16 + t;
        g_rowsum[j] = 0.0f;
        g_rowmax[j] = 0ull;
    } else if (t == 16) {
        g_colmax[i] = 0u;
        g_cnt[i] = 0u;
    }
}

// ---------------- normalize z (warp per row) ----------------
__global__ void k_zsplit(const float* __restrict__ z) {
    int row = blockIdx.x * 8 + (threadIdx.x >> 5);
    int lane = threadIdx.x & 31;
    const float4* zr = (const float4*)(z + (size_t)row * Hdim);
    float4 v[4];
    float ss = 0.0f;
#pragma unroll
    for (int q = 0; q < 4; q++) {
        v[q] = zr[q * 32 + lane];
        ss += v[q].x * v[q].x + v[q].y * v[q].y + v[q].z * v[q].z + v[q].w * v[q].w;
    }
#pragma unroll
    for (int o = 16; o; o >>= 1) ss += __shfl_xor_sync(0xffffffffu, ss, o);
    float inv = 1.0f / fmaxf(sqrtf(ss), 1e-12f);
    if (lane == 0) g_zinv[row] = inv;
    uint2* zo = (uint2*)(g_zh + (size_t)row * Hdim);
#pragma unroll
    for (int q = 0; q < 4; q++) {
        uint2 p;
        p.x = pkh(__float2half_rn(v[q].x * inv), __float2half_rn(v[q].y * inv));
        p.y = pkh(__float2half_rn(v[q].z * inv), __float2half_rn(v[q].w * inv));
        zo[q * 32 + lane] = p;
    }
}

// ---------------- transpose raw mem -> memT fp16 ----------------
__global__ void k_memT(const float* __restrict__ mem) {
    __shared__ float t[32][33];
    int h0 = blockIdx.x * 32, n0 = blockIdx.y * 32;
    int tx = threadIdx.x, ty = threadIdx.y;
#pragma unroll
    for (int i = 0; i < 4; i++)
        t[ty + 8 * i][tx] = mem[(size_t)(n0 + ty + 8 * i) * Hdim + h0 + tx];
    __syncthreads();
#pragma unroll
    for (int i = 0; i < 4; i++) {
        int h = h0 + ty + 8 * i, n = n0 + tx;
        g_mth[(size_t)h * Ndim + n] = __float2half_rn(t[tx][ty + 8 * i]);
    }
}

// ---------------- mma.sync GEMM (128x128 block, 32x64 warp tile, BK=64, 3-stage, 2 CTA/SM) ----------------
// PHASE 1: sim = zh @ mh^T -> exp, Wh, blkmax, rowsum, rowmax
// PHASE 2: zhat = Wh @ mth^T / rowsum -> out
template <int KTOT, int PHASE>
__global__ __launch_bounds__(256, 2)
void k_gemm_mma(float* __restrict__ out) {
    constexpr int NC = KTOT / 64;
    constexpr int STAGE = 2 * 16384;
    extern __shared__ __align__(128) char smraw[];
    const uint32_t smb = smem_u32(smraw);

    const int tid = threadIdx.x;
    const int lane = tid & 31;
    const int w = tid >> 5;
    const int wm = (w & 3) << 5;              // warp row base (0..96)
    const int wn = (w >> 2) << 6;             // warp col base (0/64)
    const int m0 = blockIdx.y << 7;
    const int n0 = blockIdx.x << 7;

    const __half *Ah, *Bh;
    if (PHASE == 1) { Ah = g_zh; Bh = g_mh;  }
    else            { Ah = g_Wh; Bh = g_mth; }

    int grow[4], gcol[4], gswo[4];
#pragma unroll
    for (int q = 0; q < 4; q++) {
        int id = tid + (q << 8);
        grow[q] = id >> 3;
        gcol[q] = (id & 7) << 3;
        gswo[q] = grow[q] * 128 + (((id & 7) ^ (grow[q] & 7)) << 4);
    }

    float acc[2][8][4];
#pragma unroll
    for (int i = 0; i < 2; i++)
#pragma unroll
        for (int j = 0; j < 8; j++)
#pragma unroll
            for (int q = 0; q < 4; q++) acc[i][j][q] = 0.0f;

#define LOAD_STAGE(c, s) do {                                                        \
    uint32_t sb_ = smb + (s) * STAGE;                                                \
    size_t k0_ = (size_t)((c) << 6);                                                 \
    _Pragma("unroll")                                                                \
    for (int q = 0; q < 4; q++) {                                                    \
        size_t ao_ = (size_t)(m0 + grow[q]) * KTOT + k0_ + gcol[q];                  \
        size_t bo_ = (size_t)(n0 + grow[q]) * KTOT + k0_ + gcol[q];                  \
        cp16(sb_ + gswo[q],         Ah + ao_);                                       \
        cp16(sb_ + 16384 + gswo[q], Bh + bo_);                                       \
    }                                                                                \
    CP_COMMIT();                                                                     \
} while (0)

    LOAD_STAGE(0, 0);
    LOAD_STAGE(1, 1);
    CP_WAIT(1);
    __syncthreads();

    int st = 0;
    for (int c = 0; c < NC; c++) {
        const uint32_t sA = smb + st * STAGE;
        const uint32_t sB = sA + 16384;

#pragma unroll
        for (int k16 = 0; k16 < 4; k16++) {
            uint32_t ah[2][4];
#pragma unroll
            for (int mi = 0; mi < 2; mi++) {
                int rA = wm + (mi << 4) + (lane & 15);
                int cA = (k16 << 1) + (lane >> 4);
                uint32_t off = rA * 128 + ((cA ^ (rA & 7)) << 4);
                ldsm4(ah[mi], sA + off);
            }
            uint32_t bh[4][4];
#pragma unroll
            for (int ng = 0; ng < 4; ng++) {
                int rB = wn + (ng << 4) + (lane & 7) + ((lane & 16) >> 1);
                int cB = (k16 << 1) + ((lane >> 3) & 1);
                uint32_t off = rB * 128 + ((cB ^ (rB & 7)) << 4);
                ldsm4(bh[ng], sB + off);
            }
#pragma unroll
            for (int mi = 0; mi < 2; mi++)
#pragma unroll
                for (int ng = 0; ng < 4; ng++)
#pragma unroll
                    for (int s2 = 0; s2 < 2; s2++)
                        mma16816(acc[mi][ng * 2 + s2], ah[mi], &bh[ng][s2 * 2]);
        }

        int pf = c + 2;
        int pst = st + 2; if (pst >= 3) pst -= 3;
        if (pf < NC) { LOAD_STAGE(pf, pst); } else { CP_COMMIT(); }
        CP_WAIT(1);
        __syncthreads();
        st = st + 1 == 3 ? 0 : st + 1;
    }
#undef LOAD_STAGE

    // ---------------- epilogue ----------------
    const int rq = lane >> 2;
    const int cq = (lane & 3) << 1;

    if (PHASE == 1) {
        float rs[2][2] = {{0.f, 0.f}, {0.f, 0.f}};
        float bv[2][2] = {{-1e30f, -1e30f}, {-1e30f, -1e30f}};
        int   bi[2][2] = {{0, 0}, {0, 0}};
#pragma unroll
        for (int mi = 0; mi < 2; mi++)
#pragma unroll
            for (int ni = 0; ni < 8; ni++) {
                float* cc = acc[mi][ni];
                int colb = n0 + wn + ni * 8 + cq;
#pragma unroll
                for (int h = 0; h < 2; h++) {
                    float v0 = cc[h * 2], v1 = cc[h * 2 + 1];
                    float e0 = __expf(v0), e1 = __expf(v1);
                    rs[mi][h] += e0 + e1;
                    if (v0 > bv[mi][h]) { bv[mi][h] = v0; bi[mi][h] = colb; }
                    if (v1 > bv[mi][h]) { bv[mi][h] = v1; bi[mi][h] = colb + 1; }
                    int row = m0 + wm + mi * 16 + rq + h * 8;
                    size_t o = (size_t)row * Ndim + colb;
                    *(uint32_t*)&g_Wh[o] = pkh(__float2half_rn(e0), __float2half_rn(e1));
                }
            }
#pragma unroll
        for (int mi = 0; mi < 2; mi++)
#pragma unroll
            for (int h = 0; h < 2; h++) {
#pragma unroll
                for (int o = 1; o <= 2; o <<= 1) {
                    rs[mi][h] += __shfl_xor_sync(0xffffffffu, rs[mi][h], o);
                    float ov = __shfl_xor_sync(0xffffffffu, bv[mi][h], o);
                    int   oi = __shfl_xor_sync(0xffffffffu, bi[mi][h], o);
                    if (ov > bv[mi][h]) { bv[mi][h] = ov; bi[mi][h] = oi; }
                }
                if ((lane & 3) == 0) {
                    int row = m0 + wm + mi * 16 + rq + h * 8;
                    atomicAdd(&g_rowsum[row], rs[mi][h]);
                    unsigned long long key =
                        ((unsigned long long)keyenc(bv[mi][h]) << 32) | (unsigned int)bi[mi][h];
                    atomicMax(&g_rowmax[row], key);
                    atomicMax((unsigned int*)&g_blkmax[(size_t)row * 16 + blockIdx.x],
                              keyenc(__expf(bv[mi][h])));
                }
            }
    } else {
#pragma unroll
        for (int mi = 0; mi < 2; mi++)
#pragma unroll
            for (int h = 0; h < 2; h++) {
                int row = m0 + wm + mi * 16 + rq + h * 8;
                float inv = 1.0f / g_rowsum[row];
#pragma unroll
                for (int ni = 0; ni < 8; ni++) {
                    float* cc = acc[mi][ni];
                    int col = n0 + wn + ni * 8 + cq;
                    float2 v = make_float2(cc[h * 2] * inv, cc[h * 2 + 1] * inv);
                    *(float2*)&out[(size_t)row * Hdim + col] = v;
                }
            }
    }
}

// ---------------- argmax fix + count + colmax (fused, blkmax-accelerated) ----------------
__global__ void k_argmax_fix(const float* __restrict__ z) {
    const int wid = threadIdx.x >> 5, lane = threadIdx.x & 31;
    const int row = blockIdx.x * 8 + wid;
    __shared__ int s_cnt[8];
    __shared__ int s_cand[8][16];

    float bm = -1e30f;
    if (lane < 16) bm = keydec(((const unsigned int*)g_blkmax)[(size_t)row * 16 + lane]);
    float a1 = bm;
#pragma unroll
    for (int o = 16; o; o >>= 1) a1 = fmaxf(a1, __shfl_xor_sync(0xffffffffu, a1, o));
    float thr = a1 * (1.0f - 1e-3f);

    unsigned int qmask = __ballot_sync(0xffffffffu, (lane < 16) && (bm >= thr));

    unsigned long long fkey = g_rowmax[row];

    if (lane == 0) s_cnt[wid] = 0;
    __syncwarp();

    const __half* wh = g_Wh + (size_t)row * Ndim;
    unsigned int m = qmask;
    while (m) {
        int b = __ffs(m) - 1;
        m &= m - 1;
        uint2 v2 = *(const uint2*)(wh + b * 128 + lane * 4);
        __half2 p0 = *(__half2*)&v2.x;
        __half2 p1 = *(__half2*)&v2.y;
        float w0 = __half2float(__low2half(p0));
        float w1 = __half2float(__high2half(p0));
        float w2 = __half2float(__low2half(p1));
        float w3 = __half2float(__high2half(p1));
        int jb = b * 128 + lane * 4;
        if (w0 >= thr) { int p = atomicAdd(&s_cnt[wid], 1); if (p < 16) s_cand[wid][p] = jb; }
        if (w1 >= thr) { int p = atomicAdd(&s_cnt[wid], 1); if (p < 16) s_cand[wid][p] = jb + 1; }
        if (w2 >= thr) { int p = atomicAdd(&s_cnt[wid], 1); if (p < 16) s_cand[wid][p] = jb + 2; }
        if (w3 >= thr) { int p = atomicAdd(&s_cnt[wid], 1); if (p < 16) s_cand[wid][p] = jb + 3; }
    }
    __syncwarp();
    int cnt = min(s_cnt[wid], 16);

    if (cnt >= 2) {
        float zin = g_zinv[row];
        const float* zr = z + (size_t)row * Hdim;
        float best = -1e30f;
        int bi = -1;
        for (int c = 0; c < cnt; c++) {
            int j = s_cand[wid][c];
            const float* mr = g_mn + (size_t)j * Hdim;
            float s = 0.0f;
            for (int t = 0; t < 16; t++) {
                int h = t * 32 + lane;
                s += zr[h] * zin * mr[h];
            }
#pragma unroll
            for (int o = 16; o; o >>= 1) s += __shfl_down_sync(0xffffffffu, s, o);
            s = __shfl_sync(0xffffffffu, s, 0);
            if (s > best) { best = s; bi = j; }
        }
        fkey = ((unsigned long long)keyenc(best) << 32) | (unsigned int)bi;
        if (lane == 0) g_rowmax[row] = fkey;
    }

    if (lane == 0) {
        unsigned int idx = (unsigned int)(fkey & 0xFFFFFFFFull);
        atomicAdd(&g_cnt[idx], 1u);
        atomicMax(&g_colmax[idx], (unsigned int)(fkey >> 32));
    }
}

// ---------------- prefix scan + row-list fill (single block, smem atomics) ----------------
__global__ void k_prefix_fill() {
    __shared__ unsigned int sa[Ndim], sb[Ndim], scur[Ndim];
    int t = threadIdx.x;                       // 1024 threads
    sa[t] = g_cnt[t]; sa[t + 1024] = g_cnt[t + 1024];
    __syncthreads();
    unsigned int* src = sa;
    unsigned int* dst = sb;
    for (int d = 1; d < Ndim; d <<= 1) {
#pragma unroll
        for (int q = 0; q < 2; q++) {
            int i = t + q * 1024;
            dst[i] = src[i] + (i >= d ? src[i - d] : 0u);
        }
        __syncthreads();
        unsigned int* tmp = src; src = dst; dst = tmp;
    }
#pragma unroll
    for (int q = 0; q < 2; q++) {
        int i = t + q * 1024;
        unsigned int excl = src[i] - g_cnt[i];
        g_off[i] = excl;
        scur[i] = excl;
    }
    __syncthreads();
    // fill: scatter rows into per-slot segments via smem cursors
    for (int r = t; r < Bdim; r += 1024) {
        unsigned int idx = (unsigned int)(g_rowmax[r] & 0xFFFFFFFFull);
        unsigned int pos = atomicAdd(&scur[idx], 1u);
        g_rowlist[pos] = (unsigned int)r;
    }
}

// ---------------- per-slot update + finalize (no atomics) ----------------
__global__ void k_update(const float* __restrict__ z, const float* __restrict__ mem,
                         float* __restrict__ out) {
    int n = blockIdx.x;
    int t = threadIdx.x;
    const float* mr = mem + (size_t)n * Hdim;
    float* o = out + (size_t)Bdim * Hdim + (size_t)n * Hdim;
    int cnt = (int)g_cnt[n];
    if (cnt == 0) {
        o[t] = mr[t];
        o[t + 256] = mr[t + 256];
        return;
    }
    float cm = keydec(g_colmax[n]);
    int off = (int)g_off[n];
    float a0 = 0.0f, a1 = 0.0f, denom = 0.0f;
    int r = 0;
    for (; r + 2 <= cnt; r += 2) {
        int rowA = (int)g_rowlist[off + r];
        int rowB = (int)g_rowlist[off + r + 1];
        unsigned long long kA = g_rowmax[rowA];
        unsigned long long kB = g_rowmax[rowB];
        float pA = __expf(keydec((unsigned int)(kA >> 32)) - cm);
        float pB = __expf(keydec((unsigned int)(kB >> 32)) - cm);
        const float* zA = z + (size_t)rowA * Hdim;
        const float* zB = z + (size_t)rowB * Hdim;
        float zA0 = zA[t], zA1 = zA[t + 256];
        float zB0 = zB[t], zB1 = zB[t + 256];
        denom += pA + pB;
        a0 += pA * zA0 + pB * zB0;
        a1 += pA * zA1 + pB * zB1;
    }
    if (r < cnt) {
        int row = (int)g_rowlist[off + r];
        unsigned long long key = g_rowmax[row];
        float p = __expf(keydec((unsigned int)(key >> 32)) - cm);
        denom += p;
        const float* zr = z + (size_t)row * Hdim;
        a0 += p * zr[t];
        a1 += p * zr[t + 256];
    }
    float invd = 1.0f / denom;
    float v0 = mr[t] + a0 * invd;
    float v1 = mr[t + 256] + a1 * invd;
    __shared__ float red[256];
    red[t] = v0 * v0 + v1 * v1;
    __syncthreads();
    for (int s = 128; s > 0; s >>= 1) {
        if (t < s) red[t] += red[t + s];
        __syncthreads();
    }
    float inv = 1.0f / fmaxf(sqrtf(red[0]), 1e-12f);
    o[t] = v0 * inv;
    o[t + 256] = v1 * inv;
}

// ---------------- launch ----------------
extern "C" void kernel_launch(void* const* d_in, const int* in_sizes, int n_in,
                              void* d_out, int out_size) {
    (void)in_sizes; (void)n_in; (void)out_size;
    const float* z   = (const float*)d_in[0];
    const float* mem = (const float*)d_in[1];
    float* out = (float*)d_out;

    const int DS = 3 * 2 * 16384;   // 96KB
    cudaFuncSetAttribute(k_gemm_mma<Hdim, 1>, cudaFuncAttributeMaxDynamicSharedMemorySize, DS);
    cudaFuncSetAttribute(k_gemm_mma<Ndim, 2>, cudaFuncAttributeMaxDynamicSharedMemorySize, DS);

    k_norm_mem<<<Ndim, 256>>>(mem);                                    // 0
    k_zsplit<<<Bdim / 8, 256>>>(z);                                    // 1
    k_memT<<<dim3(Hdim / 32, Ndim / 32), dim3(32, 8)>>>(mem);          // 2
    k_gemm_mma<Hdim, 1><<<dim3(Ndim / 128, Bdim / 128), 256, DS>>>(nullptr);  // 3
    k_argmax_fix<<<Bdim / 8, 256>>>(z);                                // 4
    k_prefix_fill<<<1, 1024>>>();                                      // 5
    k_gemm_mma<Ndim, 2><<<dim3(Hdim / 128, Bdim / 128), 256, DS>>>(out);      // 6
    k_update<<<Ndim, 256>>>(z, mem, out);                              // 7
}

// round 13
// speedup vs baseline: 1.0357x; 1.0357x over previous
#include <cuda_runtime.h>
#include <cuda_fp16.h>
#include <math.h>
#include <stdint.h>

#define Bdim 32768
#define Ndim 2048
#define Hdim 512

// ---------------- scratch (device globals; no allocation allowed) ----------------
__device__ __align__(16) float g_mn[Ndim * Hdim];            // normalized memory fp32
__device__ float g_zinv[Bdim];
__device__ __align__(16) __half g_zh[(size_t)Bdim * Hdim];   // normalized z fp16
__device__ __align__(16) __half g_mh[Ndim * Hdim];           // normalized mem fp16
__device__ __align__(16) __half g_mth[Hdim * Ndim];          // mem^T fp16 (raw mem)
__device__ __align__(16) __half g_Wh[(size_t)Bdim * Ndim];   // exp(sim) fp16
__device__ __align__(16) float g_blkmax[(size_t)Bdim * 16];  // per (row, 128-col block) max of W (keyenc)
__device__ float g_rowsum[Bdim];
__device__ unsigned long long g_rowmax[Bdim];                // (keyenc(val)<<32)|idx
__device__ unsigned int g_colmax[Ndim];
__device__ unsigned int g_cnt[Ndim];
__device__ unsigned int g_off[Ndim];
__device__ unsigned int g_cur[Ndim];
__device__ unsigned int g_rowlist[Bdim];

// ---------------- helpers ----------------
__device__ __forceinline__ unsigned int keyenc(float f) {
    unsigned int b = __float_as_uint(f);
    return (b & 0x80000000u) ? ~b : (b | 0x80000000u);
}
__device__ __forceinline__ float keydec(unsigned int v) {
    unsigned int b = (v & 0x80000000u) ? (v ^ 0x80000000u) : ~v;
    return __uint_as_float(b);
}
__device__ __forceinline__ unsigned int pkh(__half a, __half b) {
    return ((unsigned int)__half_as_ushort(b) << 16) | (unsigned int)__half_as_ushort(a);
}
__device__ __forceinline__ uint32_t smem_u32(const void* p) {
    uint32_t a;
    asm("{ .reg .u64 t; cvta.to.shared.u64 t, %1; cvt.u32.u64 %0, t; }" : "=r"(a) : "l"(p));
    return a;
}

__device__ __forceinline__ void cp16(uint32_t d, const void* s) {
    asm volatile("cp.async.cg.shared.global [%0], [%1], 16;" :: "r"(d), "l"(s));
}
#define CP_COMMIT() asm volatile("cp.async.commit_group;" ::: "memory")
#define CP_WAIT(n)  asm volatile("cp.async.wait_group %0;" :: "n"(n) : "memory")

__device__ __forceinline__ void ldsm4(uint32_t* r, uint32_t a) {
    asm volatile("ldmatrix.sync.aligned.m8n8.x4.shared.b16 {%0,%1,%2,%3}, [%4];"
        : "=r"(r[0]), "=r"(r[1]), "=r"(r[2]), "=r"(r[3]) : "r"(a));
}
__device__ __forceinline__ void mma16816(float* c, const uint32_t* a, const uint32_t* b) {
    asm volatile(
        "mma.sync.aligned.m16n8k16.row.col.f32.f16.f16.f32 "
        "{%0,%1,%2,%3},{%4,%5,%6,%7},{%8,%9},{%0,%1,%2,%3};"
        : "+f"(c[0]), "+f"(c[1]), "+f"(c[2]), "+f"(c[3])
        : "r"(a[0]), "r"(a[1]), "r"(a[2]), "r"(a[3]), "r"(b[0]), "r"(b[1]));
}

// ---------------- normalize memory + zero scratch (incl. blkmax) ----------------
__global__ void k_norm_mem(const float* __restrict__ mem) {
    int i = blockIdx.x;
    int t = threadIdx.x;
    __shared__ float red[256];
    const float* r = mem + (size_t)i * Hdim;
    float v0 = r[t];
    float v1 = r[t + 256];
    red[t] = v0 * v0 + v1 * v1;
    __syncthreads();
    for (int s = 128; s > 0; s >>= 1) {
        if (t < s) red[t] += red[t + s];
        __syncthreads();
    }
    float inv = 1.0f / fmaxf(sqrtf(red[0]), 1e-12f);
    float n0 = v0 * inv, n1 = v1 * inv;
    size_t b = (size_t)i * Hdim + t;
    g_mn[b] = n0; g_mn[b + 256] = n1;
    g_mh[b] = __float2half_rn(n0);
    g_mh[b + 256] = __float2half_rn(n1);
    // scratch zeroing: 2048 blocks cover Bdim rows (16/block) and blkmax (256/block)
    ((unsigned int*)g_blkmax)[i * 256 + t] = 0u;
    if (t < 16) {
        int j = i * 16 + t;
        g_rowsum[j] = 0.0f;
        g_rowmax[j] = 0ull;
    } else if (t == 16) {
        g_colmax[i] = 0u;
        g_cnt[i] = 0u;
    }
}

// ---------------- normalize z (warp per row) ----------------
__global__ void k_zsplit(const float* __restrict__ z) {
    int row = blockIdx.x * 8 + (threadIdx.x >> 5);
    int lane = threadIdx.x & 31;
    const float4* zr = (const float4*)(z + (size_t)row * Hdim);
    float4 v[4];
    float ss = 0.0f;
#pragma unroll
    for (int q = 0; q < 4; q++) {
        v[q] = zr[q * 32 + lane];
        ss += v[q].x * v[q].x + v[q].y * v[q].y + v[q].z * v[q].z + v[q].w * v[q].w;
    }
#pragma unroll
    for (int o = 16; o; o >>= 1) ss += __shfl_xor_sync(0xffffffffu, ss, o);
    float inv = 1.0f / fmaxf(sqrtf(ss), 1e-12f);
    if (lane == 0) g_zinv[row] = inv;
    uint2* zo = (uint2*)(g_zh + (size_t)row * Hdim);
#pragma unroll
    for (int q = 0; q < 4; q++) {
        uint2 p;
        p.x = pkh(__float2half_rn(v[q].x * inv), __float2half_rn(v[q].y * inv));
        p.y = pkh(__float2half_rn(v[q].z * inv), __float2half_rn(v[q].w * inv));
        zo[q * 32 + lane] = p;
    }
}

// ---------------- transpose raw mem -> memT fp16 ----------------
__global__ void k_memT(const float* __restrict__ mem) {
    __shared__ float t[32][33];
    int h0 = blockIdx.x * 32, n0 = blockIdx.y * 32;
    int tx = threadIdx.x, ty = threadIdx.y;
#pragma unroll
    for (int i = 0; i < 4; i++)
        t[ty + 8 * i][tx] = mem[(size_t)(n0 + ty + 8 * i) * Hdim + h0 + tx];
    __syncthreads();
#pragma unroll
    for (int i = 0; i < 4; i++) {
        int h = h0 + ty + 8 * i, n = n0 + tx;
        g_mth[(size_t)h * Ndim + n] = __float2half_rn(t[tx][ty + 8 * i]);
    }
}

// ---------------- mma.sync GEMM (128x128 block, 32x64 warp tile, BK=64, 3-stage, 2 CTA/SM) ----------------
// PHASE 1: sim = zh @ mh^T -> exp, Wh, blkmax, rowsum, rowmax
// PHASE 2: zhat = Wh @ mth^T / rowsum -> out
template <int KTOT, int PHASE>
__global__ __launch_bounds__(256, 2)
void k_gemm_mma(float* __restrict__ out) {
    constexpr int NC = KTOT / 64;
    constexpr int STAGE = 2 * 16384;
    extern __shared__ __align__(128) char smraw[];
    const uint32_t smb = smem_u32(smraw);

    const int tid = threadIdx.x;
    const int lane = tid & 31;
    const int w = tid >> 5;
    const int wm = (w & 3) << 5;              // warp row base (0..96)
    const int wn = (w >> 2) << 6;             // warp col base (0/64)
    const int m0 = blockIdx.y << 7;
    const int n0 = blockIdx.x << 7;

    const __half *Ah, *Bh;
    if (PHASE == 1) { Ah = g_zh; Bh = g_mh;  }
    else            { Ah = g_Wh; Bh = g_mth; }

    int grow[4], gcol[4], gswo[4];
#pragma unroll
    for (int q = 0; q < 4; q++) {
        int id = tid + (q << 8);
        grow[q] = id >> 3;
        gcol[q] = (id & 7) << 3;
        gswo[q] = grow[q] * 128 + (((id & 7) ^ (grow[q] & 7)) << 4);
    }

    float acc[2][8][4];
#pragma unroll
    for (int i = 0; i < 2; i++)
#pragma unroll
        for (int j = 0; j < 8; j++)
#pragma unroll
            for (int q = 0; q < 4; q++) acc[i][j][q] = 0.0f;

#define LOAD_STAGE(c, s) do {                                                        \
    uint32_t sb_ = smb + (s) * STAGE;                                                \
    size_t k0_ = (size_t)((c) << 6);                                                 \
    _Pragma("unroll")                                                                \
    for (int q = 0; q < 4; q++) {                                                    \
        size_t ao_ = (size_t)(m0 + grow[q]) * KTOT + k0_ + gcol[q];                  \
        size_t bo_ = (size_t)(n0 + grow[q]) * KTOT + k0_ + gcol[q];                  \
        cp16(sb_ + gswo[q],         Ah + ao_);                                       \
        cp16(sb_ + 16384 + gswo[q], Bh + bo_);                                       \
    }                                                                                \
    CP_COMMIT();                                                                     \
} while (0)

    LOAD_STAGE(0, 0);
    LOAD_STAGE(1, 1);
    CP_WAIT(1);
    __syncthreads();

    int st = 0;
    for (int c = 0; c < NC; c++) {
        const uint32_t sA = smb + st * STAGE;
        const uint32_t sB = sA + 16384;

#pragma unroll
        for (int k16 = 0; k16 < 4; k16++) {
            uint32_t ah[2][4];
#pragma unroll
            for (int mi = 0; mi < 2; mi++) {
                int rA = wm + (mi << 4) + (lane & 15);
                int cA = (k16 << 1) + (lane >> 4);
                uint32_t off = rA * 128 + ((cA ^ (rA & 7)) << 4);
                ldsm4(ah[mi], sA + off);
            }
            uint32_t bh[4][4];
#pragma unroll
            for (int ng = 0; ng < 4; ng++) {
                int rB = wn + (ng << 4) + (lane & 7) + ((lane & 16) >> 1);
                int cB = (k16 << 1) + ((lane >> 3) & 1);
                uint32_t off = rB * 128 + ((cB ^ (rB & 7)) << 4);
                ldsm4(bh[ng], sB + off);
            }
#pragma unroll
            for (int mi = 0; mi < 2; mi++)
#pragma unroll
                for (int ng = 0; ng < 4; ng++)
#pragma unroll
                    for (int s2 = 0; s2 < 2; s2++)
                        mma16816(acc[mi][ng * 2 + s2], ah[mi], &bh[ng][s2 * 2]);
        }

        int pf = c + 2;
        int pst = st + 2; if (pst >= 3) pst -= 3;
        if (pf < NC) { LOAD_STAGE(pf, pst); } else { CP_COMMIT(); }
        CP_WAIT(1);
        __syncthreads();
        st = st + 1 == 3 ? 0 : st + 1;
    }
#undef LOAD_STAGE

    // ---------------- epilogue ----------------
    const int rq = lane >> 2;
    const int cq = (lane & 3) << 1;

    if (PHASE == 1) {
        float rs[2][2] = {{0.f, 0.f}, {0.f, 0.f}};
        float bv[2][2] = {{-1e30f, -1e30f}, {-1e30f, -1e30f}};
        int   bi[2][2] = {{0, 0}, {0, 0}};
#pragma unroll
        for (int mi = 0; mi < 2; mi++)
#pragma unroll
            for (int ni = 0; ni < 8; ni++) {
                float* cc = acc[mi][ni];
                int colb = n0 + wn + ni * 8 + cq;
#pragma unroll
                for (int h = 0; h < 2; h++) {
                    float v0 = cc[h * 2], v1 = cc[h * 2 + 1];
                    float e0 = __expf(v0), e1 = __expf(v1);
                    rs[mi][h] += e0 + e1;
                    if (v0 > bv[mi][h]) { bv[mi][h] = v0; bi[mi][h] = colb; }
                    if (v1 > bv[mi][h]) { bv[mi][h] = v1; bi[mi][h] = colb + 1; }
                    int row = m0 + wm + mi * 16 + rq + h * 8;
                    size_t o = (size_t)row * Ndim + colb;
                    *(uint32_t*)&g_Wh[o] = pkh(__float2half_rn(e0), __float2half_rn(e1));
                }
            }
#pragma unroll
        for (int mi = 0; mi < 2; mi++)
#pragma unroll
            for (int h = 0; h < 2; h++) {
#pragma unroll
                for (int o = 1; o <= 2; o <<= 1) {
                    rs[mi][h] += __shfl_xor_sync(0xffffffffu, rs[mi][h], o);
                    float ov = __shfl_xor_sync(0xffffffffu, bv[mi][h], o);
                    int   oi = __shfl_xor_sync(0xffffffffu, bi[mi][h], o);
                    if (ov > bv[mi][h]) { bv[mi][h] = ov; bi[mi][h] = oi; }
                }
                if ((lane & 3) == 0) {
                    int row = m0 + wm + mi * 16 + rq + h * 8;
                    atomicAdd(&g_rowsum[row], rs[mi][h]);
                    unsigned long long key =
                        ((unsigned long long)keyenc(bv[mi][h]) << 32) | (unsigned int)bi[mi][h];
                    atomicMax(&g_rowmax[row], key);
                    atomicMax((unsigned int*)&g_blkmax[(size_t)row * 16 + blockIdx.x],
                              keyenc(__expf(bv[mi][h])));
                }
            }
    } else {
#pragma unroll
        for (int mi = 0; mi < 2; mi++)
#pragma unroll
            for (int h = 0; h < 2; h++) {
                int row = m0 + wm + mi * 16 + rq + h * 8;
                float inv = 1.0f / g_rowsum[row];
#pragma unroll
                for (int ni = 0; ni < 8; ni++) {
                    float* cc = acc[mi][ni];
                    int col = n0 + wn + ni * 8 + cq;
                    float2 v = make_float2(cc[h * 2] * inv, cc[h * 2 + 1] * inv);
                    *(float2*)&out[(size_t)row * Hdim + col] = v;
                }
            }
    }
}

// ---------------- argmax fix + count + colmax (fused, blkmax-accelerated) ----------------
__global__ void k_argmax_fix(const float* __restrict__ z) {
    const int wid = threadIdx.x >> 5, lane = threadIdx.x & 31;
    const int row = blockIdx.x * 8 + wid;
    __shared__ int s_cnt[8];
    __shared__ int s_cand[8][16];

    float bm = -1e30f;
    if (lane < 16) bm = keydec(((const unsigned int*)g_blkmax)[(size_t)row * 16 + lane]);
    float a1 = bm;
#pragma unroll
    for (int o = 16; o; o >>= 1) a1 = fmaxf(a1, __shfl_xor_sync(0xffffffffu, a1, o));
    float thr = a1 * (1.0f - 1e-3f);

    unsigned int qmask = __ballot_sync(0xffffffffu, (lane < 16) && (bm >= thr));

    unsigned long long fkey = g_rowmax[row];

    if (lane == 0) s_cnt[wid] = 0;
    __syncwarp();

    const __half* wh = g_Wh + (size_t)row * Ndim;
    unsigned int m = qmask;
    while (m) {
        int b = __ffs(m) - 1;
        m &= m - 1;
        uint2 v2 = *(const uint2*)(wh + b * 128 + lane * 4);
        __half2 p0 = *(__half2*)&v2.x;
        __half2 p1 = *(__half2*)&v2.y;
        float w0 = __half2float(__low2half(p0));
        float w1 = __half2float(__high2half(p0));
        float w2 = __half2float(__low2half(p1));
        float w3 = __half2float(__high2half(p1));
        int jb = b * 128 + lane * 4;
        if (w0 >= thr) { int p = atomicAdd(&s_cnt[wid], 1); if (p < 16) s_cand[wid][p] = jb; }
        if (w1 >= thr) { int p = atomicAdd(&s_cnt[wid], 1); if (p < 16) s_cand[wid][p] = jb + 1; }
        if (w2 >= thr) { int p = atomicAdd(&s_cnt[wid], 1); if (p < 16) s_cand[wid][p] = jb + 2; }
        if (w3 >= thr) { int p = atomicAdd(&s_cnt[wid], 1); if (p < 16) s_cand[wid][p] = jb + 3; }
    }
    __syncwarp();
    int cnt = min(s_cnt[wid], 16);

    if (cnt >= 2) {
        float zin = g_zinv[row];
        const float* zr = z + (size_t)row * Hdim;
        float best = -1e30f;
        int bi = -1;
        for (int c = 0; c < cnt; c++) {
            int j = s_cand[wid][c];
            const float* mr = g_mn + (size_t)j * Hdim;
            float s = 0.0f;
            for (int t = 0; t < 16; t++) {
                int h = t * 32 + lane;
                s += zr[h] * zin * mr[h];
            }
#pragma unroll
            for (int o = 16; o; o >>= 1) s += __shfl_down_sync(0xffffffffu, s, o);
            s = __shfl_sync(0xffffffffu, s, 0);
            if (s > best) { best = s; bi = j; }
        }
        fkey = ((unsigned long long)keyenc(best) << 32) | (unsigned int)bi;
        if (lane == 0) g_rowmax[row] = fkey;
    }

    if (lane == 0) {
        unsigned int idx = (unsigned int)(fkey & 0xFFFFFFFFull);
        atomicAdd(&g_cnt[idx], 1u);
        atomicMax(&g_colmax[idx], (unsigned int)(fkey >> 32));
    }
}

// ---------------- exclusive prefix scan over 2048 counts (one block) ----------------
__global__ void k_prefix() {
    __shared__ unsigned int sa[Ndim], sb[Ndim];
    int t = threadIdx.x;
    sa[t] = g_cnt[t]; sa[t + 1024] = g_cnt[t + 1024];
    __syncthreads();
    unsigned int* src = sa;
    unsigned int* dst = sb;
    for (int d = 1; d < Ndim; d <<= 1) {
#pragma unroll
        for (int q = 0; q < 2; q++) {
            int i = t + q * 1024;
            dst[i] = src[i] + (i >= d ? src[i - d] : 0u);
        }
        __syncthreads();
        unsigned int* tmp = src; src = dst; dst = tmp;
    }
#pragma unroll
    for (int q = 0; q < 2; q++) {
        int i = t + q * 1024;
        unsigned int excl = src[i] - g_cnt[i];
        g_off[i] = excl;
        g_cur[i] = excl;
    }
}

// ---------------- fill row list ----------------
__global__ void k_fill() {
    int b = blockIdx.x * blockDim.x + threadIdx.x;
    if (b >= Bdim) return;
    unsigned int idx = (unsigned int)(g_rowmax[b] & 0xFFFFFFFFull);
    unsigned int pos = atomicAdd(&g_cur[idx], 1u);
    g_rowlist[pos] = (unsigned int)b;
}

// ---------------- per-slot update + finalize (no atomics) ----------------
__global__ void k_update(const float* __restrict__ z, const float* __restrict__ mem,
                         float* __restrict__ out) {
    int n = blockIdx.x;
    int t = threadIdx.x;
    const float* mr = mem + (size_t)n * Hdim;
    float* o = out + (size_t)Bdim * Hdim + (size_t)n * Hdim;
    int cnt = (int)g_cnt[n];
    if (cnt == 0) {
        o[t] = mr[t];
        o[t + 256] = mr[t + 256];
        return;
    }
    float cm = keydec(g_colmax[n]);
    int off = (int)g_off[n];
    float a0 = 0.0f, a1 = 0.0f, denom = 0.0f;
    int r = 0;
    for (; r + 2 <= cnt; r += 2) {
        int rowA = (int)g_rowlist[off + r];
        int rowB = (int)g_rowlist[off + r + 1];
        unsigned long long kA = g_rowmax[rowA];
        unsigned long long kB = g_rowmax[rowB];
        float pA = __expf(keydec((unsigned int)(kA >> 32)) - cm);
        float pB = __expf(keydec((unsigned int)(kB >> 32)) - cm);
        const float* zA = z + (size_t)rowA * Hdim;
        const float* zB = z + (size_t)rowB * Hdim;
        float zA0 = zA[t], zA1 = zA[t + 256];
        float zB0 = zB[t], zB1 = zB[t + 256];
        denom += pA + pB;
        a0 += pA * zA0 + pB * zB0;
        a1 += pA * zA1 + pB * zB1;
    }
    if (r < cnt) {
        int row = (int)g_rowlist[off + r];
        unsigned long long key = g_rowmax[row];
        float p = __expf(keydec((unsigned int)(key >> 32)) - cm);
        denom += p;
        const float* zr = z + (size_t)row * Hdim;
        a0 += p * zr[t];
        a1 += p * zr[t + 256];
    }
    float invd = 1.0f / denom;
    float v0 = mr[t] + a0 * invd;
    float v1 = mr[t + 256] + a1 * invd;
    __shared__ float red[256];
    red[t] = v0 * v0 + v1 * v1;
    __syncthreads();
    for (int s = 128; s > 0; s >>= 1) {
        if (t < s) red[t] += red[t + s];
        __syncthreads();
    }
    float inv = 1.0f / fmaxf(sqrtf(red[0]), 1e-12f);
    o[t] = v0 * inv;
    o[t + 256] = v1 * inv;
}

// ---------------- launch ----------------
extern "C" void kernel_launch(void* const* d_in, const int* in_sizes, int n_in,
                              void* d_out, int out_size) {
    (void)in_sizes; (void)n_in; (void)out_size;
    const float* z   = (const float*)d_in[0];
    const float* mem = (const float*)d_in[1];
    float* out = (float*)d_out;

    const int DS = 3 * 2 * 16384;   // 96KB
    cudaFuncSetAttribute(k_gemm_mma<Hdim, 1>, cudaFuncAttributeMaxDynamicSharedMemorySize, DS);
    cudaFuncSetAttribute(k_gemm_mma<Ndim, 2>, cudaFuncAttributeMaxDynamicSharedMemorySize, DS);

    k_norm_mem<<<Ndim, 256>>>(mem);                                    // 0
    k_zsplit<<<Bdim / 8, 256>>>(z);                                    // 1
    k_memT<<<dim3(Hdim / 32, Ndim / 32), dim3(32, 8)>>>(mem);          // 2
    k_gemm_mma<Hdim, 1><<<dim3(Ndim / 128, Bdim / 128), 256, DS>>>(nullptr);  // 3
    k_argmax_fix<<<Bdim / 8, 256>>>(z);                                // 4
    k_prefix<<<1, 1024>>>();                                           // 5
    k_fill<<<Bdim / 256, 256>>>();                                     // 6
    k_gemm_mma<Ndim, 2><<<dim3(Ndim / 128 / 4, Bdim / 128), 256, DS>>>(out);  // 7 (grid 4x256 = Hdim/128 x Bdim/128)
    k_update<<<Ndim, 256>>>(z, mem, out);                              // 8
}

// round 14
// speedup vs baseline: 1.0419x; 1.0060x over previous
#include <cuda_runtime.h>
#include <cuda_fp16.h>
#include <math.h>
#include <stdint.h>

#define Bdim 32768
#define Ndim 2048
#define Hdim 512

// ---------------- scratch (device globals; no allocation allowed) ----------------
__device__ __align__(16) float g_mn[Ndim * Hdim];            // normalized memory fp32
__device__ float g_zinv[Bdim];
__device__ __align__(16) __half g_zh[(size_t)Bdim * Hdim];   // normalized z fp16
__device__ __align__(16) __half g_mh[Ndim * Hdim];           // normalized mem fp16
__device__ __align__(16) __half g_mth[Hdim * Ndim];          // mem^T fp16 (raw mem)
__device__ __align__(16) __half g_Wh[(size_t)Bdim * Ndim];   // exp(sim) fp16
__device__ __align__(16) float g_blkmax[(size_t)Bdim * 16];  // per (row, 128-col block) max of W (keyenc)
__device__ float g_rowsum[Bdim];
__device__ unsigned long long g_rowmax[Bdim];                // (keyenc(val)<<32)|idx
__device__ unsigned int g_colmax[Ndim];
__device__ unsigned int g_cnt[Ndim];
__device__ unsigned int g_off[Ndim];
__device__ unsigned int g_cur[Ndim];
__device__ unsigned int g_rowlist[Bdim];

// ---------------- helpers ----------------
__device__ __forceinline__ unsigned int keyenc(float f) {
    unsigned int b = __float_as_uint(f);
    return (b & 0x80000000u) ? ~b : (b | 0x80000000u);
}
__device__ __forceinline__ float keydec(unsigned int v) {
    unsigned int b = (v & 0x80000000u) ? (v ^ 0x80000000u) : ~v;
    return __uint_as_float(b);
}
// pack two fp32 into half2 with rn rounding in ONE instruction
__device__ __forceinline__ unsigned int pkf2h(float lo, float hi) {
    unsigned int r;
    asm("cvt.rn.f16x2.f32 %0, %1, %2;" : "=r"(r) : "f"(hi), "f"(lo));
    return r;
}
__device__ __forceinline__ uint32_t smem_u32(const void* p) {
    uint32_t a;
    asm("{ .reg .u64 t; cvta.to.shared.u64 t, %1; cvt.u32.u64 %0, t; }" : "=r"(a) : "l"(p));
    return a;
}

__device__ __forceinline__ void cp16(uint32_t d, const void* s) {
    asm volatile("cp.async.cg.shared.global [%0], [%1], 16;" :: "r"(d), "l"(s));
}
#define CP_COMMIT() asm volatile("cp.async.commit_group;" ::: "memory")
#define CP_WAIT(n)  asm volatile("cp.async.wait_group %0;" :: "n"(n) : "memory")

__device__ __forceinline__ void ldsm4(uint32_t* r, uint32_t a) {
    asm volatile("ldmatrix.sync.aligned.m8n8.x4.shared.b16 {%0,%1,%2,%3}, [%4];"
        : "=r"(r[0]), "=r"(r[1]), "=r"(r[2]), "=r"(r[3]) : "r"(a));
}
__device__ __forceinline__ void mma16816(float* c, const uint32_t* a, const uint32_t* b) {
    asm volatile(
        "mma.sync.aligned.m16n8k16.row.col.f32.f16.f16.f32 "
        "{%0,%1,%2,%3},{%4,%5,%6,%7},{%8,%9},{%0,%1,%2,%3};"
        : "+f"(c[0]), "+f"(c[1]), "+f"(c[2]), "+f"(c[3])
        : "r"(a[0]), "r"(a[1]), "r"(a[2]), "r"(a[3]), "r"(b[0]), "r"(b[1]));
}

// ---------------- normalize memory + zero scratch (incl. blkmax) ----------------
__global__ void k_norm_mem(const float* __restrict__ mem) {
    int i = blockIdx.x;
    int t = threadIdx.x;
    __shared__ float red[256];
    const float* r = mem + (size_t)i * Hdim;
    float v0 = r[t];
    float v1 = r[t + 256];
    red[t] = v0 * v0 + v1 * v1;
    __syncthreads();
    for (int s = 128; s > 0; s >>= 1) {
        if (t < s) red[t] += red[t + s];
        __syncthreads();
    }
    float inv = 1.0f / fmaxf(sqrtf(red[0]), 1e-12f);
    float n0 = v0 * inv, n1 = v1 * inv;
    size_t b = (size_t)i * Hdim + t;
    g_mn[b] = n0; g_mn[b + 256] = n1;
    g_mh[b] = __float2half_rn(n0);
    g_mh[b + 256] = __float2half_rn(n1);
    // scratch zeroing: 2048 blocks cover Bdim rows (16/block) and blkmax (256/block)
    ((unsigned int*)g_blkmax)[i * 256 + t] = 0u;
    if (t < 16) {
        int j = i * 16 + t;
        g_rowsum[j] = 0.0f;
        g_rowmax[j] = 0ull;
    } else if (t == 16) {
        g_colmax[i] = 0u;
        g_cnt[i] = 0u;
    }
}

// ---------------- normalize z (warp per row) ----------------
__global__ void k_zsplit(const float* __restrict__ z) {
    int row = blockIdx.x * 8 + (threadIdx.x >> 5);
    int lane = threadIdx.x & 31;
    const float4* zr = (const float4*)(z + (size_t)row * Hdim);
    float4 v[4];
    float ss = 0.0f;
#pragma unroll
    for (int q = 0; q < 4; q++) {
        v[q] = zr[q * 32 + lane];
        ss += v[q].x * v[q].x + v[q].y * v[q].y + v[q].z * v[q].z + v[q].w * v[q].w;
    }
#pragma unroll
    for (int o = 16; o; o >>= 1) ss += __shfl_xor_sync(0xffffffffu, ss, o);
    float inv = 1.0f / fmaxf(sqrtf(ss), 1e-12f);
    if (lane == 0) g_zinv[row] = inv;
    uint2* zo = (uint2*)(g_zh + (size_t)row * Hdim);
#pragma unroll
    for (int q = 0; q < 4; q++) {
        uint2 p;
        p.x = pkf2h(v[q].x * inv, v[q].y * inv);
        p.y = pkf2h(v[q].z * inv, v[q].w * inv);
        zo[q * 32 + lane] = p;
    }
}

// ---------------- transpose raw mem -> memT fp16 ----------------
__global__ void k_memT(const float* __restrict__ mem) {
    __shared__ float t[32][33];
    int h0 = blockIdx.x * 32, n0 = blockIdx.y * 32;
    int tx = threadIdx.x, ty = threadIdx.y;
#pragma unroll
    for (int i = 0; i < 4; i++)
        t[ty + 8 * i][tx] = mem[(size_t)(n0 + ty + 8 * i) * Hdim + h0 + tx];
    __syncthreads();
#pragma unroll
    for (int i = 0; i < 4; i++) {
        int h = h0 + ty + 8 * i, n = n0 + tx;
        g_mth[(size_t)h * Ndim + n] = __float2half_rn(t[tx][ty + 8 * i]);
    }
}

// ---------------- mma.sync GEMM (128x128 block, 32x64 warp tile, BK=64, 3-stage, 2 CTA/SM) ----------------
// PHASE 1: sim = zh @ mh^T -> exp, Wh, blkmax, rowsum, rowmax
// PHASE 2: zhat = Wh @ mth^T / rowsum -> out
template <int KTOT, int PHASE>
__global__ __launch_bounds__(256, 2)
void k_gemm_mma(float* __restrict__ out) {
    constexpr int NC = KTOT / 64;
    constexpr int STAGE = 2 * 16384;
    extern __shared__ __align__(128) char smraw[];
    const uint32_t smb = smem_u32(smraw);

    const int tid = threadIdx.x;
    const int lane = tid & 31;
    const int w = tid >> 5;
    const int wm = (w & 3) << 5;              // warp row base (0..96)
    const int wn = (w >> 2) << 6;             // warp col base (0/64)
    const int m0 = blockIdx.y << 7;
    const int n0 = blockIdx.x << 7;

    const __half *Ah, *Bh;
    if (PHASE == 1) { Ah = g_zh; Bh = g_mh;  }
    else            { Ah = g_Wh; Bh = g_mth; }

    int grow[4], gcol[4], gswo[4];
#pragma unroll
    for (int q = 0; q < 4; q++) {
        int id = tid + (q << 8);
        grow[q] = id >> 3;
        gcol[q] = (id & 7) << 3;
        gswo[q] = grow[q] * 128 + (((id & 7) ^ (grow[q] & 7)) << 4);
    }

    float acc[2][8][4];
#pragma unroll
    for (int i = 0; i < 2; i++)
#pragma unroll
        for (int j = 0; j < 8; j++)
#pragma unroll
            for (int q = 0; q < 4; q++) acc[i][j][q] = 0.0f;

#define LOAD_STAGE(c, s) do {                                                        \
    uint32_t sb_ = smb + (s) * STAGE;                                                \
    size_t k0_ = (size_t)((c) << 6);                                                 \
    _Pragma("unroll")                                                                \
    for (int q = 0; q < 4; q++) {                                                    \
        size_t ao_ = (size_t)(m0 + grow[q]) * KTOT + k0_ + gcol[q];                  \
        size_t bo_ = (size_t)(n0 + grow[q]) * KTOT + k0_ + gcol[q];                  \
        cp16(sb_ + gswo[q],         Ah + ao_);                                       \
        cp16(sb_ + 16384 + gswo[q], Bh + bo_);                                       \
    }                                                                                \
    CP_COMMIT();                                                                     \
} while (0)

    LOAD_STAGE(0, 0);
    LOAD_STAGE(1, 1);
    CP_WAIT(1);
    __syncthreads();

    int st = 0;
    for (int c = 0; c < NC; c++) {
        const uint32_t sA = smb + st * STAGE;
        const uint32_t sB = sA + 16384;

#pragma unroll
        for (int k16 = 0; k16 < 4; k16++) {
            uint32_t ah[2][4];
#pragma unroll
            for (int mi = 0; mi < 2; mi++) {
                int rA = wm + (mi << 4) + (lane & 15);
                int cA = (k16 << 1) + (lane >> 4);
                uint32_t off = rA * 128 + ((cA ^ (rA & 7)) << 4);
                ldsm4(ah[mi], sA + off);
            }
            uint32_t bh[4][4];
#pragma unroll
            for (int ng = 0; ng < 4; ng++) {
                int rB = wn + (ng << 4) + (lane & 7) + ((lane & 16) >> 1);
                int cB = (k16 << 1) + ((lane >> 3) & 1);
                uint32_t off = rB * 128 + ((cB ^ (rB & 7)) << 4);
                ldsm4(bh[ng], sB + off);
            }
#pragma unroll
            for (int mi = 0; mi < 2; mi++)
#pragma unroll
                for (int ng = 0; ng < 4; ng++)
#pragma unroll
                    for (int s2 = 0; s2 < 2; s2++)
                        mma16816(acc[mi][ng * 2 + s2], ah[mi], &bh[ng][s2 * 2]);
        }

        int pf = c + 2;
        int pst = st + 2; if (pst >= 3) pst -= 3;
        if (pf < NC) { LOAD_STAGE(pf, pst); } else { CP_COMMIT(); }
        CP_WAIT(1);
        __syncthreads();
        st = st + 1 == 3 ? 0 : st + 1;
    }
#undef LOAD_STAGE

    // ---------------- epilogue ----------------
    const int rq = lane >> 2;
    const int cq = (lane & 3) << 1;

    if (PHASE == 1) {
        float rs[2][2] = {{0.f, 0.f}, {0.f, 0.f}};
        float bv[2][2] = {{-1e30f, -1e30f}, {-1e30f, -1e30f}};
        int   bi[2][2] = {{0, 0}, {0, 0}};
#pragma unroll
        for (int mi = 0; mi < 2; mi++)
#pragma unroll
            for (int ni = 0; ni < 8; ni++) {
                float* cc = acc[mi][ni];
                int colb = n0 + wn + ni * 8 + cq;
#pragma unroll
                for (int h = 0; h < 2; h++) {
                    float v0 = cc[h * 2], v1 = cc[h * 2 + 1];
                    float e0 = __expf(v0), e1 = __expf(v1);
                    rs[mi][h] += e0 + e1;
                    if (v0 > bv[mi][h]) { bv[mi][h] = v0; bi[mi][h] = colb; }
                    if (v1 > bv[mi][h]) { bv[mi][h] = v1; bi[mi][h] = colb + 1; }
                    int row = m0 + wm + mi * 16 + rq + h * 8;
                    size_t o = (size_t)row * Ndim + colb;
                    *(uint32_t*)&g_Wh[o] = pkf2h(e0, e1);   // single cvt.rn.f16x2.f32
                }
            }
#pragma unroll
        for (int mi = 0; mi < 2; mi++)
#pragma unroll
            for (int h = 0; h < 2; h++) {
#pragma unroll
                for (int o = 1; o <= 2; o <<= 1) {
                    rs[mi][h] += __shfl_xor_sync(0xffffffffu, rs[mi][h], o);
                    float ov = __shfl_xor_sync(0xffffffffu, bv[mi][h], o);
                    int   oi = __shfl_xor_sync(0xffffffffu, bi[mi][h], o);
                    if (ov > bv[mi][h]) { bv[mi][h] = ov; bi[mi][h] = oi; }
                }
                if ((lane & 3) == 0) {
                    int row = m0 + wm + mi * 16 + rq + h * 8;
                    atomicAdd(&g_rowsum[row], rs[mi][h]);
                    unsigned long long key =
                        ((unsigned long long)keyenc(bv[mi][h]) << 32) | (unsigned int)bi[mi][h];
                    atomicMax(&g_rowmax[row], key);
                    atomicMax((unsigned int*)&g_blkmax[(size_t)row * 16 + blockIdx.x],
                              keyenc(__expf(bv[mi][h])));
                }
            }
    } else {
#pragma unroll
        for (int mi = 0; mi < 2; mi++)
#pragma unroll
            for (int h = 0; h < 2; h++) {
                int row = m0 + wm + mi * 16 + rq + h * 8;
                float inv = 1.0f / g_rowsum[row];
#pragma unroll
                for (int ni = 0; ni < 8; ni++) {
                    float* cc = acc[mi][ni];
                    int col = n0 + wn + ni * 8 + cq;
                    float2 v = make_float2(cc[h * 2] * inv, cc[h * 2 + 1] * inv);
                    *(float2*)&out[(size_t)row * Hdim + col] = v;
                }
            }
    }
}

// ---------------- argmax fix + count + colmax (fused, blkmax-accelerated) ----------------
__global__ void k_argmax_fix(const float* __restrict__ z) {
    const int wid = threadIdx.x >> 5, lane = threadIdx.x & 31;
    const int row = blockIdx.x * 8 + wid;
    __shared__ int s_cnt[8];
    __shared__ int s_cand[8][16];

    float bm = -1e30f;
    if (lane < 16) bm = keydec(((const unsigned int*)g_blkmax)[(size_t)row * 16 + lane]);
    float a1 = bm;
#pragma unroll
    for (int o = 16; o; o >>= 1) a1 = fmaxf(a1, __shfl_xor_sync(0xffffffffu, a1, o));
    float thr = a1 * (1.0f - 1e-3f);

    unsigned int qmask = __ballot_sync(0xffffffffu, (lane < 16) && (bm >= thr));

    unsigned long long fkey = g_rowmax[row];

    if (lane == 0) s_cnt[wid] = 0;
    __syncwarp();

    const __half* wh = g_Wh + (size_t)row * Ndim;
    unsigned int m = qmask;
    while (m) {
        int b = __ffs(m) - 1;
        m &= m - 1;
        uint2 v2 = *(const uint2*)(wh + b * 128 + lane * 4);
        __half2 p0 = *(__half2*)&v2.x;
        __half2 p1 = *(__half2*)&v2.y;
        float w0 = __half2float(__low2half(p0));
        float w1 = __half2float(__high2half(p0));
        float w2 = __half2float(__low2half(p1));
        float w3 = __half2float(__high2half(p1));
        int jb = b * 128 + lane * 4;
        if (w0 >= thr) { int p = atomicAdd(&s_cnt[wid], 1); if (p < 16) s_cand[wid][p] = jb; }
        if (w1 >= thr) { int p = atomicAdd(&s_cnt[wid], 1); if (p < 16) s_cand[wid][p] = jb + 1; }
        if (w2 >= thr) { int p = atomicAdd(&s_cnt[wid], 1); if (p < 16) s_cand[wid][p] = jb + 2; }
        if (w3 >= thr) { int p = atomicAdd(&s_cnt[wid], 1); if (p < 16) s_cand[wid][p] = jb + 3; }
    }
    __syncwarp();
    int cnt = min(s_cnt[wid], 16);

    if (cnt >= 2) {
        float zin = g_zinv[row];
        const float* zr = z + (size_t)row * Hdim;
        float best = -1e30f;
        int bi = -1;
        for (int c = 0; c < cnt; c++) {
            int j = s_cand[wid][c];
            const float* mr = g_mn + (size_t)j * Hdim;
            float s = 0.0f;
            for (int t = 0; t < 16; t++) {
                int h = t * 32 + lane;
                s += zr[h] * zin * mr[h];
            }
#pragma unroll
            for (int o = 16; o; o >>= 1) s += __shfl_down_sync(0xffffffffu, s, o);
            s = __shfl_sync(0xffffffffu, s, 0);
            if (s > best) { best = s; bi = j; }
        }
        fkey = ((unsigned long long)keyenc(best) << 32) | (unsigned int)bi;
        if (lane == 0) g_rowmax[row] = fkey;
    }

    if (lane == 0) {
        unsigned int idx = (unsigned int)(fkey & 0xFFFFFFFFull);
        atomicAdd(&g_cnt[idx], 1u);
        atomicMax(&g_colmax[idx], (unsigned int)(fkey >> 32));
    }
}

// ---------------- exclusive prefix scan over 2048 counts (one block) ----------------
__global__ void k_prefix() {
    __shared__ unsigned int sa[Ndim], sb[Ndim];
    int t = threadIdx.x;
    sa[t] = g_cnt[t]; sa[t + 1024] = g_cnt[t + 1024];
    __syncthreads();
    unsigned int* src = sa;
    unsigned int* dst = sb;
    for (int d = 1; d < Ndim; d <<= 1) {
#pragma unroll
        for (int q = 0; q < 2; q++) {
            int i = t + q * 1024;
            dst[i] = src[i] + (i >= d ? src[i - d] : 0u);
        }
        __syncthreads();
        unsigned int* tmp = src; src = dst; dst = tmp;
    }
#pragma unroll
    for (int q = 0; q < 2; q++) {
        int i = t + q * 1024;
        unsigned int excl = src[i] - g_cnt[i];
        g_off[i] = excl;
        g_cur[i] = excl;
    }
}

// ---------------- fill row list ----------------
__global__ void k_fill() {
    int b = blockIdx.x * blockDim.x + threadIdx.x;
    if (b >= Bdim) return;
    unsigned int idx = (unsigned int)(g_rowmax[b] & 0xFFFFFFFFull);
    unsigned int pos = atomicAdd(&g_cur[idx], 1u);
    g_rowlist[pos] = (unsigned int)b;
}

// ---------------- per-slot update + finalize (no atomics) ----------------
__global__ void k_update(const float* __restrict__ z, const float* __restrict__ mem,
                         float* __restrict__ out) {
    int n = blockIdx.x;
    int t = threadIdx.x;
    const float* mr = mem + (size_t)n * Hdim;
    float* o = out + (size_t)Bdim * Hdim + (size_t)n * Hdim;
    int cnt = (int)g_cnt[n];
    if (cnt == 0) {
        o[t] = mr[t];
        o[t + 256] = mr[t + 256];
        return;
    }
    float cm = keydec(g_colmax[n]);
    int off = (int)g_off[n];
    float a0 = 0.0f, a1 = 0.0f, denom = 0.0f;
    int r = 0;
    for (; r + 2 <= cnt; r += 2) {
        int rowA = (int)g_rowlist[off + r];
        int rowB = (int)g_rowlist[off + r + 1];
        unsigned long long kA = g_rowmax[rowA];
        unsigned long long kB = g_rowmax[rowB];
        float pA = __expf(keydec((unsigned int)(kA >> 32)) - cm);
        float pB = __expf(keydec((unsigned int)(kB >> 32)) - cm);
        const float* zA = z + (size_t)rowA * Hdim;
        const float* zB = z + (size_t)rowB * Hdim;
        float zA0 = zA[t], zA1 = zA[t + 256];
        float zB0 = zB[t], zB1 = zB[t + 256];
        denom += pA + pB;
        a0 += pA * zA0 + pB * zB0;
        a1 += pA * zA1 + pB * zB1;
    }
    if (r < cnt) {
        int row = (int)g_rowlist[off + r];
        unsigned long long key = g_rowmax[row];
        float p = __expf(keydec((unsigned int)(key >> 32)) - cm);
        denom += p;
        const float* zr = z + (size_t)row * Hdim;
        a0 += p * zr[t];
        a1 += p * zr[t + 256];
    }
    float invd = 1.0f / denom;
    float v0 = mr[t] + a0 * invd;
    float v1 = mr[t + 256] + a1 * invd;
    __shared__ float red[256];
    red[t] = v0 * v0 + v1 * v1;
    __syncthreads();
    for (int s = 128; s > 0; s >>= 1) {
        if (t < s) red[t] += red[t + s];
        __syncthreads();
    }
    float inv = 1.0f / fmaxf(sqrtf(red[0]), 1e-12f);
    o[t] = v0 * inv;
    o[t + 256] = v1 * inv;
}

// ---------------- launch ----------------
extern "C" void kernel_launch(void* const* d_in, const int* in_sizes, int n_in,
                              void* d_out, int out_size) {
    (void)in_sizes; (void)n_in; (void)out_size;
    const float* z   = (const float*)d_in[0];
    const float* mem = (const float*)d_in[1];
    float* out = (float*)d_out;

    const int DS = 3 * 2 * 16384;   // 96KB
    cudaFuncSetAttribute(k_gemm_mma<Hdim, 1>, cudaFuncAttributeMaxDynamicSharedMemorySize, DS);
    cudaFuncSetAttribute(k_gemm_mma<Ndim, 2>, cudaFuncAttributeMaxDynamicSharedMemorySize, DS);

    k_norm_mem<<<Ndim, 256>>>(mem);                                    // 0
    k_zsplit<<<Bdim / 8, 256>>>(z);                                    // 1
    k_memT<<<dim3(Hdim / 32, Ndim / 32), dim3(32, 8)>>>(mem);          // 2
    k_gemm_mma<Hdim, 1><<<dim3(Ndim / 128, Bdim / 128), 256, DS>>>(nullptr);  // 3
    k_argmax_fix<<<Bdim / 8, 256>>>(z);                                // 4
    k_prefix<<<1, 1024>>>();                                           // 5
    k_fill<<<Bdim / 256, 256>>>();                                     // 6
    k_gemm_mma<Ndim, 2><<<dim3(Hdim / 128, Bdim / 128), 256, DS>>>(out);      // 7
    k_update<<<Ndim, 256>>>(z, mem, out);                              // 8
}